// round 5
// baseline (speedup 1.0000x reference)
#include <cuda_runtime.h>
#include <cuda_bf16.h>
#include <math.h>

#define BB 16
#define TT 4096
#define DD 512
#define CCH 10
#define FWD 100
#define KW 201          // 2*FW+1
#define NBLK 4          // N split: 4 tiles of 128 columns

// ---------------- device scratch (static, allowed) ----------------
__device__ __align__(16) __nv_bfloat16 g_Whi[DD * DD];
__device__ __align__(16) __nv_bfloat16 g_Wlo[DD * DD];
__device__ __align__(16) __nv_bfloat16 g_Vhi[(size_t)BB * TT * DD];
__device__ __align__(16) __nv_bfloat16 g_Vlo[(size_t)BB * TT * DD];
__device__ float g_dec[BB * DD];                 // dec projection + b_enc
__device__ float g_conv[BB * TT * CCH];          // conv features [b][t][c]
__device__ float g_epart[NBLK * BB * TT];        // partial logits per N-block
__device__ float g_ctxpart[8 * BB * DD];         // context partials per T-chunk

// ---------------- helpers ----------------
__device__ __forceinline__ unsigned pack_bf2(float x, float y) {
    __nv_bfloat162 h = __floats2bfloat162_rn(x, y);
    return *reinterpret_cast<unsigned*>(&h);
}
__device__ __forceinline__ float tanh_fast(float x) {
    float ax = fabsf(x);
    float z = __expf(-2.0f * ax);
    float t = __fdividef(1.0f - z, 1.0f + z);
    return copysignf(t, x);
}

__device__ __forceinline__ void mma_bf16(float* d, const unsigned* a,
                                         unsigned b0, unsigned b1) {
    asm volatile(
        "mma.sync.aligned.m16n8k16.row.col.f32.bf16.bf16.f32 "
        "{%0,%1,%2,%3}, {%4,%5,%6,%7}, {%8,%9}, {%0,%1,%2,%3};\n"
        : "+f"(d[0]), "+f"(d[1]), "+f"(d[2]), "+f"(d[3])
        : "r"(a[0]), "r"(a[1]), "r"(a[2]), "r"(a[3]), "r"(b0), "r"(b1));
}

__device__ __forceinline__ void ldsm4(unsigned* r, unsigned addr) {
    asm volatile("ldmatrix.sync.aligned.m8n8.x4.shared.b16 {%0,%1,%2,%3}, [%4];\n"
                 : "=r"(r[0]), "=r"(r[1]), "=r"(r[2]), "=r"(r[3]) : "r"(addr));
}

#define CP_ASYNC16(sm, gm) \
    asm volatile("cp.async.cg.shared.global [%0], [%1], 16;\n" :: "r"(sm), "l"(gm))
#define CP_COMMIT() asm volatile("cp.async.commit_group;\n")
#define CP_WAIT(n)  asm volatile("cp.async.wait_group %0;\n" :: "n"(n))

// ---------------- kernel 1: split W_enc into bf16 hi/lo ----------------
__global__ void k_split(const float* __restrict__ W) {
    int i = blockIdx.x * blockDim.x + threadIdx.x;
    float w = W[i];
    __nv_bfloat16 hi = __float2bfloat16(w);
    g_Whi[i] = hi;
    g_Wlo[i] = __float2bfloat16(w - __bfloat162float(hi));
}

// ---------------- kernel 1b: split value into bf16 hi/lo ----------------
__global__ void __launch_bounds__(256) k_vsplit(const float* __restrict__ v) {
    size_t i = ((size_t)blockIdx.x * 256 + threadIdx.x) * 4;
    float4 x = *(const float4*)(v + i);
    __nv_bfloat16 h0 = __float2bfloat16(x.x);
    __nv_bfloat16 h1 = __float2bfloat16(x.y);
    __nv_bfloat16 h2 = __float2bfloat16(x.z);
    __nv_bfloat16 h3 = __float2bfloat16(x.w);
    __nv_bfloat162 ph0; ph0.x = h0; ph0.y = h1;
    __nv_bfloat162 ph1; ph1.x = h2; ph1.y = h3;
    uint2 hv = make_uint2(*(unsigned*)&ph0, *(unsigned*)&ph1);
    uint2 lv = make_uint2(pack_bf2(x.x - __bfloat162float(h0),
                                   x.y - __bfloat162float(h1)),
                          pack_bf2(x.z - __bfloat162float(h2),
                                   x.w - __bfloat162float(h3)));
    *reinterpret_cast<uint2*>(g_Vhi + i) = hv;
    *reinterpret_cast<uint2*>(g_Vlo + i) = lv;
}

// ---------------- kernel 2: dec projection + b_enc ----------------
__global__ void k_dec(const float* __restrict__ query,
                      const float* __restrict__ Wdec,
                      const float* __restrict__ b_enc) {
    __shared__ float q[DD];
    int b = blockIdx.x;
    int e = threadIdx.x;
    q[e] = query[b * DD + e];
    __syncthreads();
    float acc = b_enc[e];
    const float* wr = Wdec + e * DD;
#pragma unroll 8
    for (int d = 0; d < DD; ++d) acc += q[d] * wr[d];
    g_dec[b * DD + e] = acc;
}

// ---------------- kernel 3: location conv (att_prev -> [b][t][10]) ------
__global__ void k_conv(const float* __restrict__ att_prev,
                       const float* __restrict__ Wconv) {
    __shared__ float win[128 + 2 * FWD];
    __shared__ float wc[CCH * KW];
    int t0 = blockIdx.x * 128;
    int b = blockIdx.y;
    int tid = threadIdx.x;                 // 128
    for (int i = tid; i < 128 + 2 * FWD; i += 128) {
        int gidx = t0 - FWD + i;
        win[i] = (gidx >= 0 && gidx < TT) ? att_prev[b * TT + gidx] : 0.f;
    }
    for (int i = tid; i < CCH * KW; i += 128) wc[i] = Wconv[i];
    __syncthreads();
    float acc[CCH];
#pragma unroll
    for (int c = 0; c < CCH; ++c) acc[c] = 0.f;
    for (int h = 0; h < KW; ++h) {
        float x = win[tid + h];
#pragma unroll
        for (int c = 0; c < CCH; ++c) acc[c] += x * wc[c * KW + h];
    }
    float* o = &g_conv[(size_t)(b * TT + t0 + tid) * CCH];
#pragma unroll
    for (int c = 0; c < CCH; ++c) o[c] = acc[c];
}

// ---------------- kernel 4: fused split-bf16 GEMM + epilogue -> logits --
// block tile: 128(t) x 128(e), KC=16, double-buffered cp.async,
// 512 threads (16 warps 4x4), 1 CTA/SM, ~32 accum regs/thread (no spills)
#define KC 16
#define NCHUNK (DD / KC)   // 32
struct SMain {
    unsigned Ahi[2][128][12];   // [stage][row][8 used + 4 pad] rows 48B
    unsigned Alo[2][128][12];
    unsigned Bhi[2][128][12];
    unsigned Blo[2][128][12];
};                              // 49152 bytes
struct SEpi {
    float conv[128][10];
    float watt[128][10];
    float dec[128];
    float wg[128];
    float red[128][4];
};
union SU { SMain m; SEpi e; };

__global__ void __launch_bounds__(512, 1)
k_gemm(const float* __restrict__ Watt,
       const float* __restrict__ wg) {
    __shared__ SU su;
    int tid = threadIdx.x;
    int b = blockIdx.z;
    int t0 = blockIdx.x * 128;
    int e0 = blockIdx.y * 128;
    int lane = tid & 31, warp = tid >> 5;
    int wm = warp & 3, wn = warp >> 2;         // 4 x 4 warps: 32 rows x 32 cols
    int g = lane >> 2, c = lane & 3;

    float acc[2][4][4];
#pragma unroll
    for (int mt = 0; mt < 2; ++mt)
#pragma unroll
        for (int nt = 0; nt < 4; ++nt)
#pragma unroll
            for (int q = 0; q < 4; ++q) acc[mt][nt][q] = 0.f;

    unsigned sAhi = (unsigned)__cvta_generic_to_shared(&su.m.Ahi[0][0][0]);
    unsigned sAlo = (unsigned)__cvta_generic_to_shared(&su.m.Alo[0][0][0]);
    unsigned sBhi = (unsigned)__cvta_generic_to_shared(&su.m.Bhi[0][0][0]);
    unsigned sBlo = (unsigned)__cvta_generic_to_shared(&su.m.Blo[0][0][0]);

    // cp.async mapping: 512 threads -> (row 0..127, half16B 0..1, pair A/B)
    int crow = tid >> 2, q4 = tid & 3;
    int chalf = q4 & 1, cpair = q4 >> 1;       // 0 = A arrays, 1 = B arrays
    const __nv_bfloat16* gHi;
    const __nv_bfloat16* gLo;
    if (cpair == 0) {
        gHi = g_Vhi + ((size_t)(b * TT + t0 + crow)) * DD + chalf * 8;
        gLo = g_Vlo + ((size_t)(b * TT + t0 + crow)) * DD + chalf * 8;
    } else {
        gHi = g_Whi + (size_t)(e0 + crow) * DD + chalf * 8;
        gLo = g_Wlo + (size_t)(e0 + crow) * DD + chalf * 8;
    }
    unsigned dHi = (cpair == 0) ? sAhi : sBhi;
    unsigned dLo = (cpair == 0) ? sAlo : sBlo;
    unsigned soff = (unsigned)((crow * 12 + chalf * 4) * 4);   // bytes

#define ISSUE_STAGE(s, k0)                                                   \
    do {                                                                     \
        unsigned sb = (unsigned)(s) * 128u * 12u * 4u + soff;                \
        CP_ASYNC16(dHi + sb, gHi + (k0));                                    \
        CP_ASYNC16(dLo + sb, gLo + (k0));                                    \
    } while (0)

    // ldmatrix per-lane address components
    int lr = ((lane >> 3) & 1) * 8 + (lane & 7);
    int lc = ((lane >> 4) & 1) * 4;

    ISSUE_STAGE(0, 0); CP_COMMIT();
    ISSUE_STAGE(1, KC); CP_COMMIT();

    for (int it = 0; it < NCHUNK; ++it) {
        if (it < NCHUNK - 1) { CP_WAIT(1); } else { CP_WAIT(0); }
        __syncthreads();
        int s = it & 1;
        unsigned stb = (unsigned)s * 128u * 12u * 4u;

        unsigned ahi[2][4], alo[2][4];
#pragma unroll
        for (int mt = 0; mt < 2; ++mt) {
            unsigned ao = stb + (unsigned)(((wm * 32 + mt * 16 + lr) * 12 + lc) * 4);
            ldsm4(ahi[mt], sAhi + ao);
            ldsm4(alo[mt], sAlo + ao);
        }
#pragma unroll
        for (int ntp = 0; ntp < 2; ++ntp) {
            unsigned bo = stb + (unsigned)(((wn * 32 + ntp * 16 + lr) * 12 + lc) * 4);
            unsigned bh[4], bl[4];
            ldsm4(bh, sBhi + bo);
            ldsm4(bl, sBlo + bo);
#pragma unroll
            for (int sub = 0; sub < 2; ++sub) {
                int nt = ntp * 2 + sub;
                unsigned bh0 = bh[sub], bh1 = bh[2 + sub];
                unsigned bl0 = bl[sub], bl1 = bl[2 + sub];
#pragma unroll
                for (int mt = 0; mt < 2; ++mt) {
                    mma_bf16(acc[mt][nt], ahi[mt], bh0, bh1);
                    mma_bf16(acc[mt][nt], ahi[mt], bl0, bl1);
                    mma_bf16(acc[mt][nt], alo[mt], bh0, bh1);
                }
            }
        }
        __syncthreads();
        if (it < NCHUNK - 2) { ISSUE_STAGE(s, (it + 2) * KC); CP_COMMIT(); }
    }

    // ---- epilogue: + dec + conv@Watt, tanh, dot w_g, row-reduce ----
    for (int i = tid; i < 1280; i += 512) {
        int row = i / 10, cc = i - row * 10;
        su.e.conv[row][cc] = g_conv[(size_t)(b * TT + t0 + row) * CCH + cc];
        su.e.watt[row][cc] = Watt[(e0 + row) * CCH + cc];
    }
    if (tid < 128) {
        su.e.dec[tid] = g_dec[b * DD + e0 + tid];
        su.e.wg[tid] = wg[e0 + tid];
    }
    __syncthreads();

    float rowsum[2][2];
#pragma unroll
    for (int mt = 0; mt < 2; ++mt)
#pragma unroll
        for (int rr = 0; rr < 2; ++rr) {
            int rowl = wm * 32 + mt * 16 + rr * 8 + g;
            float sacc = 0.f;
#pragma unroll
            for (int nt = 0; nt < 4; ++nt)
#pragma unroll
                for (int q = 0; q < 2; ++q) {
                    int el = wn * 32 + nt * 8 + 2 * c + q;
                    float v = acc[mt][nt][rr * 2 + q] + su.e.dec[el];
#pragma unroll
                    for (int cc = 0; cc < CCH; ++cc)
                        v += su.e.conv[rowl][cc] * su.e.watt[el][cc];
                    sacc += su.e.wg[el] * tanh_fast(v);
                }
            rowsum[mt][rr] = sacc;
        }
#pragma unroll
    for (int mt = 0; mt < 2; ++mt)
#pragma unroll
        for (int rr = 0; rr < 2; ++rr) {
            float v = rowsum[mt][rr];
            v += __shfl_xor_sync(0xffffffffu, v, 1);
            v += __shfl_xor_sync(0xffffffffu, v, 2);
            rowsum[mt][rr] = v;
        }
    if (c == 0) {
#pragma unroll
        for (int mt = 0; mt < 2; ++mt)
#pragma unroll
            for (int rr = 0; rr < 2; ++rr)
                su.e.red[wm * 32 + mt * 16 + rr * 8 + g][wn] = rowsum[mt][rr];
    }
    __syncthreads();
    if (tid < 128) {
        float val = su.e.red[tid][0] + su.e.red[tid][1] +
                    su.e.red[tid][2] + su.e.red[tid][3];
        g_epart[((size_t)blockIdx.y * BB + b) * TT + t0 + tid] = val;
    }
}

// ---------------- kernel 5: masked sharpened softmax ----------------
__global__ void k_softmax(const int* __restrict__ lens,
                          float* __restrict__ out_att) {
    int b = blockIdx.x;
    int tid = threadIdx.x;            // 256
    int len = lens[b];
    __shared__ float sred[256];
    float ev[16];
    float lmax = -INFINITY;
#pragma unroll
    for (int i = 0; i < 16; ++i) {
        int t = tid + i * 256;
        float e = g_epart[(0 * BB + b) * TT + t] +
                  g_epart[(1 * BB + b) * TT + t] +
                  g_epart[(2 * BB + b) * TT + t] +
                  g_epart[(3 * BB + b) * TT + t];
        e *= 2.0f;                    // sharpening
        ev[i] = (t < len) ? e : -INFINITY;
        lmax = fmaxf(lmax, ev[i]);
    }
    sred[tid] = lmax;
    __syncthreads();
    for (int s = 128; s > 0; s >>= 1) {
        if (tid < s) sred[tid] = fmaxf(sred[tid], sred[tid + s]);
        __syncthreads();
    }
    float m = sred[0];
    __syncthreads();
    float lsum = 0.f;
#pragma unroll
    for (int i = 0; i < 16; ++i) {
        float p = expf(ev[i] - m);
        ev[i] = p;
        lsum += p;
    }
    sred[tid] = lsum;
    __syncthreads();
    for (int s = 128; s > 0; s >>= 1) {
        if (tid < s) sred[tid] += sred[tid + s];
        __syncthreads();
    }
    float inv = 1.f / sred[0];
#pragma unroll
    for (int i = 0; i < 16; ++i)
        out_att[b * TT + tid + i * 256] = ev[i] * inv;
}

// ---------------- kernel 6/7: context = value^T @ weights ----------------
__global__ void k_ctx_part(const float* __restrict__ value,
                           const float* __restrict__ att) {
    int dch = blockIdx.x, tch = blockIdx.y, b = blockIdx.z;
    int dl = threadIdx.x & 127;
    int tl = threadIdx.x >> 7;
    int d = dch * 128 + dl;
    const float* vb = value + (size_t)b * TT * DD;
    const float* ab = att + b * TT;
    float acc = 0.f;
    int tbase = tch * 512;
    for (int t = tbase + tl; t < tbase + 512; t += 2)
        acc += vb[(size_t)t * DD + d] * ab[t];
    __shared__ float s[256];
    s[threadIdx.x] = acc;
    __syncthreads();
    if (tl == 0)
        g_ctxpart[((size_t)tch * BB + b) * DD + d] = s[dl] + s[dl + 128];
}

__global__ void k_ctx_final(float* __restrict__ out) {
    int idx = blockIdx.x * 256 + threadIdx.x;
    float v = 0.f;
#pragma unroll
    for (int p = 0; p < 8; ++p) v += g_ctxpart[p * BB * DD + idx];
    out[idx] = v;
}

// ---------------- launch ----------------
extern "C" void kernel_launch(void* const* d_in, const int* in_sizes, int n_in,
                              void* d_out, int out_size) {
    const float* value    = (const float*)d_in[0];
    const float* query    = (const float*)d_in[1];
    const int*   lens     = (const int*)d_in[2];
    const float* att_prev = (const float*)d_in[3];
    const float* W_enc    = (const float*)d_in[4];
    const float* b_enc    = (const float*)d_in[5];
    const float* W_dec    = (const float*)d_in[6];
    const float* W_att    = (const float*)d_in[7];
    const float* W_conv   = (const float*)d_in[8];
    const float* w_g      = (const float*)d_in[9];
    // d_in[10] = b_g: uniform logit shift, cancels in softmax.

    float* out = (float*)d_out;
    float* out_att = out + BB * DD;

    k_split<<<512, 512>>>(W_enc);
    k_vsplit<<<(BB * TT * DD) / (4 * 256), 256>>>(value);
    k_dec<<<BB, DD>>>(query, W_dec, b_enc);
    k_conv<<<dim3(TT / 128, BB), 128>>>(att_prev, W_conv);
    k_gemm<<<dim3(TT / 128, NBLK, BB), 512>>>(W_att, w_g);
    k_softmax<<<BB, 256>>>(lens, out_att);
    k_ctx_part<<<dim3(4, 8, BB), 256>>>(value, out_att);
    k_ctx_final<<<BB * DD / 256, 256>>>(out);
}

// round 6
// speedup vs baseline: 1.1373x; 1.1373x over previous
#include <cuda_runtime.h>
#include <cuda_bf16.h>
#include <math.h>

#define BB 16
#define TT 4096
#define DD 512
#define CCH 10
#define FWD 100
#define KW 201          // 2*FW+1
#define NBLK 4          // N split: 4 tiles of 128 columns

// ---------------- device scratch (static, allowed) ----------------
__device__ __align__(16) __nv_bfloat16 g_Whi[DD * DD];
__device__ __align__(16) __nv_bfloat16 g_Wlo[DD * DD];
__device__ __align__(16) __nv_bfloat16 g_Vhi[(size_t)BB * TT * DD];
__device__ __align__(16) __nv_bfloat16 g_Vlo[(size_t)BB * TT * DD];
__device__ float g_dec[BB * DD];                 // dec projection + b_enc
__device__ float g_conv[BB * TT * CCH];          // conv features [b][t][c]
__device__ float g_epart[NBLK * BB * TT];        // partial logits per N-block
__device__ float g_ctxpart[8 * BB * DD];         // context partials per T-chunk

// ---------------- helpers ----------------
__device__ __forceinline__ unsigned pack_bf2(float x, float y) {
    __nv_bfloat162 h = __floats2bfloat162_rn(x, y);
    return *reinterpret_cast<unsigned*>(&h);
}
__device__ __forceinline__ float tanh_fast(float x) {
    float ax = fabsf(x);
    float z = __expf(-2.0f * ax);
    float t = __fdividef(1.0f - z, 1.0f + z);
    return copysignf(t, x);
}

__device__ __forceinline__ void mma_bf16(float* d, const unsigned* a,
                                         unsigned b0, unsigned b1) {
    asm volatile(
        "mma.sync.aligned.m16n8k16.row.col.f32.bf16.bf16.f32 "
        "{%0,%1,%2,%3}, {%4,%5,%6,%7}, {%8,%9}, {%0,%1,%2,%3};\n"
        : "+f"(d[0]), "+f"(d[1]), "+f"(d[2]), "+f"(d[3])
        : "r"(a[0]), "r"(a[1]), "r"(a[2]), "r"(a[3]), "r"(b0), "r"(b1));
}

__device__ __forceinline__ void ldsm4(unsigned* r, unsigned addr) {
    asm volatile("ldmatrix.sync.aligned.m8n8.x4.shared.b16 {%0,%1,%2,%3}, [%4];\n"
                 : "=r"(r[0]), "=r"(r[1]), "=r"(r[2]), "=r"(r[3]) : "r"(addr));
}

#define CP_ASYNC16(sm, gm) \
    asm volatile("cp.async.cg.shared.global [%0], [%1], 16;\n" :: "r"(sm), "l"(gm))
#define CP_COMMIT() asm volatile("cp.async.commit_group;\n")
#define CP_WAIT(n)  asm volatile("cp.async.wait_group %0;\n" :: "n"(n))

// ---------------- kernel 1: split W_enc into bf16 hi/lo ----------------
__global__ void k_split(const float* __restrict__ W) {
    int i = blockIdx.x * blockDim.x + threadIdx.x;
    float w = W[i];
    __nv_bfloat16 hi = __float2bfloat16(w);
    g_Whi[i] = hi;
    g_Wlo[i] = __float2bfloat16(w - __bfloat162float(hi));
}

// ---------------- kernel 1b: split value into bf16 hi/lo ----------------
__global__ void __launch_bounds__(256) k_vsplit(const float* __restrict__ v) {
    size_t i = ((size_t)blockIdx.x * 256 + threadIdx.x) * 4;
    float4 x = *(const float4*)(v + i);
    __nv_bfloat16 h0 = __float2bfloat16(x.x);
    __nv_bfloat16 h1 = __float2bfloat16(x.y);
    __nv_bfloat16 h2 = __float2bfloat16(x.z);
    __nv_bfloat16 h3 = __float2bfloat16(x.w);
    __nv_bfloat162 ph0; ph0.x = h0; ph0.y = h1;
    __nv_bfloat162 ph1; ph1.x = h2; ph1.y = h3;
    uint2 hv = make_uint2(*(unsigned*)&ph0, *(unsigned*)&ph1);
    uint2 lv = make_uint2(pack_bf2(x.x - __bfloat162float(h0),
                                   x.y - __bfloat162float(h1)),
                          pack_bf2(x.z - __bfloat162float(h2),
                                   x.w - __bfloat162float(h3)));
    *reinterpret_cast<uint2*>(g_Vhi + i) = hv;
    *reinterpret_cast<uint2*>(g_Vlo + i) = lv;
}

// ---------------- kernel 2: dec projection + b_enc ----------------
__global__ void k_dec(const float* __restrict__ query,
                      const float* __restrict__ Wdec,
                      const float* __restrict__ b_enc) {
    __shared__ float q[DD];
    int b = blockIdx.x;
    int e = threadIdx.x;
    q[e] = query[b * DD + e];
    __syncthreads();
    float acc = b_enc[e];
    const float* wr = Wdec + e * DD;
#pragma unroll 8
    for (int d = 0; d < DD; ++d) acc += q[d] * wr[d];
    g_dec[b * DD + e] = acc;
}

// ---------------- kernel 3: location conv (att_prev -> [b][t][10]) ------
__global__ void k_conv(const float* __restrict__ att_prev,
                       const float* __restrict__ Wconv) {
    __shared__ float win[128 + 2 * FWD];
    __shared__ float wc[CCH * KW];
    int t0 = blockIdx.x * 128;
    int b = blockIdx.y;
    int tid = threadIdx.x;                 // 128
    for (int i = tid; i < 128 + 2 * FWD; i += 128) {
        int gidx = t0 - FWD + i;
        win[i] = (gidx >= 0 && gidx < TT) ? att_prev[b * TT + gidx] : 0.f;
    }
    for (int i = tid; i < CCH * KW; i += 128) wc[i] = Wconv[i];
    __syncthreads();
    float acc[CCH];
#pragma unroll
    for (int c = 0; c < CCH; ++c) acc[c] = 0.f;
    for (int h = 0; h < KW; ++h) {
        float x = win[tid + h];
#pragma unroll
        for (int c = 0; c < CCH; ++c) acc[c] += x * wc[c * KW + h];
    }
    float* o = &g_conv[(size_t)(b * TT + t0 + tid) * CCH];
#pragma unroll
    for (int c = 0; c < CCH; ++c) o[c] = acc[c];
}

// ---------------- kernel 4: fused split-bf16 GEMM + epilogue -> logits --
// 128(t) x 128(e) tile, KC=32, 4-stage cp.async pipeline, 1 barrier/iter,
// 256 threads (8 warps, 4m x 2n), no register cap (1 CTA/SM).
#define KC 32
#define NCHUNK (DD / KC)       // 16
#define NSTAGE 4
#define ROWU 20                // padded row stride in uints (80 B, conflict-free)
#define ARR_BYTES (128u * ROWU * 4u)      // 10240 B per array
#define STAGE_BYTES (4u * ARR_BYTES)      // 40960 B: Ahi|Alo|Bhi|Blo
#define GEMM_SMEM (NSTAGE * STAGE_BYTES)  // 163840 B

__global__ void __launch_bounds__(256)
k_gemm(const float* __restrict__ Watt,
       const float* __restrict__ wg) {
    extern __shared__ __align__(16) char dsm[];
    int tid = threadIdx.x;
    int b = blockIdx.z;
    int t0 = blockIdx.x * 128;
    int e0 = blockIdx.y * 128;
    int lane = tid & 31, warp = tid >> 5;
    int wm = warp & 3, wn = warp >> 2;         // 4m x 2n warps
    int g = lane >> 2, c = lane & 3;

    float acc[2][8][4];
#pragma unroll
    for (int mt = 0; mt < 2; ++mt)
#pragma unroll
        for (int nt = 0; nt < 8; ++nt)
#pragma unroll
            for (int q = 0; q < 4; ++q) acc[mt][nt][q] = 0.f;

    unsigned sbase = (unsigned)__cvta_generic_to_shared(dsm);

    // cp.async mapping: thread -> rows (tid>>2) and (tid>>2)+64, seg = tid&3
    int row0 = tid >> 2, seg = tid & 3;
    unsigned so0 = (unsigned)(row0 * ROWU * 4 + seg * 16);
    unsigned so1 = so0 + 64u * ROWU * 4u;
    const __nv_bfloat16* gA0hi =
        g_Vhi + ((size_t)(b * TT + t0 + row0)) * DD + seg * 8;
    const __nv_bfloat16* gA0lo =
        g_Vlo + ((size_t)(b * TT + t0 + row0)) * DD + seg * 8;
    const __nv_bfloat16* gB0hi = g_Whi + (size_t)(e0 + row0) * DD + seg * 8;
    const __nv_bfloat16* gB0lo = g_Wlo + (size_t)(e0 + row0) * DD + seg * 8;
    const size_t ro64 = (size_t)64 * DD;

#define ISSUE_STAGE(s, k0)                                                    \
    do {                                                                      \
        unsigned sb = sbase + (unsigned)(s) * STAGE_BYTES;                    \
        CP_ASYNC16(sb + so0, gA0hi + (k0));                                   \
        CP_ASYNC16(sb + so1, gA0hi + ro64 + (k0));                            \
        CP_ASYNC16(sb + ARR_BYTES + so0, gA0lo + (k0));                       \
        CP_ASYNC16(sb + ARR_BYTES + so1, gA0lo + ro64 + (k0));                \
        CP_ASYNC16(sb + 2 * ARR_BYTES + so0, gB0hi + (k0));                   \
        CP_ASYNC16(sb + 2 * ARR_BYTES + so1, gB0hi + ro64 + (k0));            \
        CP_ASYNC16(sb + 3 * ARR_BYTES + so0, gB0lo + (k0));                   \
        CP_ASYNC16(sb + 3 * ARR_BYTES + so1, gB0lo + ro64 + (k0));            \
    } while (0)

    // ldmatrix lane addressing
    int lr = ((lane >> 3) & 1) * 8 + (lane & 7);   // row 0..15
    int lc = ((lane >> 4) & 1) * 4;                // uint col 0 or 4

    ISSUE_STAGE(0, 0); CP_COMMIT();
    ISSUE_STAGE(1, KC); CP_COMMIT();
    ISSUE_STAGE(2, 2 * KC); CP_COMMIT();

    for (int it = 0; it < NCHUNK; ++it) {
        CP_WAIT(2);
        __syncthreads();
        unsigned stb = sbase + (unsigned)(it & 3) * STAGE_BYTES;

#pragma unroll
        for (int ks = 0; ks < 2; ++ks) {
            unsigned kso = (unsigned)(ks * 32);    // 8 uints = 32 bytes
            unsigned ahi[2][4], alo[2][4];
#pragma unroll
            for (int mt = 0; mt < 2; ++mt) {
                unsigned ao = stb +
                    (unsigned)((wm * 32 + mt * 16 + lr) * ROWU * 4 + lc * 4) + kso;
                ldsm4(ahi[mt], ao);
                ldsm4(alo[mt], ao + ARR_BYTES);
            }
#pragma unroll
            for (int ntp = 0; ntp < 4; ++ntp) {
                unsigned bo = stb + 2 * ARR_BYTES +
                    (unsigned)((wn * 64 + ntp * 16 + lr) * ROWU * 4 + lc * 4) + kso;
                unsigned bh[4], bl[4];
                ldsm4(bh, bo);
                ldsm4(bl, bo + ARR_BYTES);
#pragma unroll
                for (int sub = 0; sub < 2; ++sub) {
                    int nt = ntp * 2 + sub;
                    unsigned bh0 = bh[sub], bh1 = bh[2 + sub];
                    unsigned bl0 = bl[sub], bl1 = bl[2 + sub];
#pragma unroll
                    for (int mt = 0; mt < 2; ++mt) {
                        mma_bf16(acc[mt][nt], ahi[mt], bh0, bh1);
                        mma_bf16(acc[mt][nt], ahi[mt], bl0, bl1);
                        mma_bf16(acc[mt][nt], alo[mt], bh0, bh1);
                    }
                }
            }
        }
        if (it + 3 < NCHUNK) ISSUE_STAGE((it + 3) & 3, (it + 3) * KC);
        CP_COMMIT();
    }
    __syncthreads();   // all stages consumed; safe to overlay epilogue

    // ---- epilogue smem overlay on dynamic smem ----
    float* econv = (float*)dsm;              // [128][10]
    float* ewatt = econv + 1280;             // [128][10]
    float* edec  = ewatt + 1280;             // [128]
    float* ewg   = edec + 128;               // [128]
    float* ered  = ewg + 128;                // [128][2]

    for (int i = tid; i < 1280; i += 256) {
        int row = i / 10, cc = i - row * 10;
        econv[i] = g_conv[(size_t)(b * TT + t0 + row) * CCH + cc];
        ewatt[i] = Watt[(e0 + row) * CCH + cc];
    }
    if (tid < 128) {
        edec[tid] = g_dec[b * DD + e0 + tid];
        ewg[tid] = wg[e0 + tid];
    }
    __syncthreads();

    float rowsum[2][2];
#pragma unroll
    for (int mt = 0; mt < 2; ++mt)
#pragma unroll
        for (int rr = 0; rr < 2; ++rr) {
            int rowl = wm * 32 + mt * 16 + rr * 8 + g;
            float sacc = 0.f;
#pragma unroll
            for (int nt = 0; nt < 8; ++nt)
#pragma unroll
                for (int q = 0; q < 2; ++q) {
                    int el = wn * 64 + nt * 8 + 2 * c + q;
                    float v = acc[mt][nt][rr * 2 + q] + edec[el];
#pragma unroll
                    for (int cc = 0; cc < CCH; ++cc)
                        v += econv[rowl * 10 + cc] * ewatt[el * 10 + cc];
                    sacc += ewg[el] * tanh_fast(v);
                }
            rowsum[mt][rr] = sacc;
        }
#pragma unroll
    for (int mt = 0; mt < 2; ++mt)
#pragma unroll
        for (int rr = 0; rr < 2; ++rr) {
            float v = rowsum[mt][rr];
            v += __shfl_xor_sync(0xffffffffu, v, 1);
            v += __shfl_xor_sync(0xffffffffu, v, 2);
            rowsum[mt][rr] = v;
        }
    if (c == 0) {
#pragma unroll
        for (int mt = 0; mt < 2; ++mt)
#pragma unroll
            for (int rr = 0; rr < 2; ++rr)
                ered[(wm * 32 + mt * 16 + rr * 8 + g) * 2 + wn] = rowsum[mt][rr];
    }
    __syncthreads();
    if (tid < 128) {
        float val = ered[tid * 2] + ered[tid * 2 + 1];
        g_epart[((size_t)blockIdx.y * BB + b) * TT + t0 + tid] = val;
    }
}

// ---------------- kernel 5: masked sharpened softmax ----------------
__global__ void k_softmax(const int* __restrict__ lens,
                          float* __restrict__ out_att) {
    int b = blockIdx.x;
    int tid = threadIdx.x;            // 256
    int len = lens[b];
    __shared__ float sred[256];
    float ev[16];
    float lmax = -INFINITY;
#pragma unroll
    for (int i = 0; i < 16; ++i) {
        int t = tid + i * 256;
        float e = g_epart[(0 * BB + b) * TT + t] +
                  g_epart[(1 * BB + b) * TT + t] +
                  g_epart[(2 * BB + b) * TT + t] +
                  g_epart[(3 * BB + b) * TT + t];
        e *= 2.0f;                    // sharpening
        ev[i] = (t < len) ? e : -INFINITY;
        lmax = fmaxf(lmax, ev[i]);
    }
    sred[tid] = lmax;
    __syncthreads();
    for (int s = 128; s > 0; s >>= 1) {
        if (tid < s) sred[tid] = fmaxf(sred[tid], sred[tid + s]);
        __syncthreads();
    }
    float m = sred[0];
    __syncthreads();
    float lsum = 0.f;
#pragma unroll
    for (int i = 0; i < 16; ++i) {
        float p = expf(ev[i] - m);
        ev[i] = p;
        lsum += p;
    }
    sred[tid] = lsum;
    __syncthreads();
    for (int s = 128; s > 0; s >>= 1) {
        if (tid < s) sred[tid] += sred[tid + s];
        __syncthreads();
    }
    float inv = 1.f / sred[0];
#pragma unroll
    for (int i = 0; i < 16; ++i)
        out_att[b * TT + tid + i * 256] = ev[i] * inv;
}

// ---------------- kernel 6/7: context = value^T @ weights ----------------
__global__ void k_ctx_part(const float* __restrict__ value,
                           const float* __restrict__ att) {
    int dch = blockIdx.x, tch = blockIdx.y, b = blockIdx.z;
    int dl = threadIdx.x & 127;
    int tl = threadIdx.x >> 7;
    int d = dch * 128 + dl;
    const float* vb = value + (size_t)b * TT * DD;
    const float* ab = att + b * TT;
    float acc = 0.f;
    int tbase = tch * 512;
    for (int t = tbase + tl; t < tbase + 512; t += 2)
        acc += vb[(size_t)t * DD + d] * ab[t];
    __shared__ float s[256];
    s[threadIdx.x] = acc;
    __syncthreads();
    if (tl == 0)
        g_ctxpart[((size_t)tch * BB + b) * DD + d] = s[dl] + s[dl + 128];
}

__global__ void k_ctx_final(float* __restrict__ out) {
    int idx = blockIdx.x * 256 + threadIdx.x;
    float v = 0.f;
#pragma unroll
    for (int p = 0; p < 8; ++p) v += g_ctxpart[p * BB * DD + idx];
    out[idx] = v;
}

// ---------------- launch ----------------
extern "C" void kernel_launch(void* const* d_in, const int* in_sizes, int n_in,
                              void* d_out, int out_size) {
    const float* value    = (const float*)d_in[0];
    const float* query    = (const float*)d_in[1];
    const int*   lens     = (const int*)d_in[2];
    const float* att_prev = (const float*)d_in[3];
    const float* W_enc    = (const float*)d_in[4];
    const float* b_enc    = (const float*)d_in[5];
    const float* W_dec    = (const float*)d_in[6];
    const float* W_att    = (const float*)d_in[7];
    const float* W_conv   = (const float*)d_in[8];
    const float* w_g      = (const float*)d_in[9];
    // d_in[10] = b_g: uniform logit shift, cancels in softmax.

    float* out = (float*)d_out;
    float* out_att = out + BB * DD;

    cudaFuncSetAttribute(k_gemm, cudaFuncAttributeMaxDynamicSharedMemorySize,
                         GEMM_SMEM);

    k_split<<<512, 512>>>(W_enc);
    k_vsplit<<<(BB * TT * DD) / (4 * 256), 256>>>(value);
    k_dec<<<BB, DD>>>(query, W_dec, b_enc);
    k_conv<<<dim3(TT / 128, BB), 128>>>(att_prev, W_conv);
    k_gemm<<<dim3(TT / 128, NBLK, BB), 256, GEMM_SMEM>>>(W_att, w_g);
    k_softmax<<<BB, 256>>>(lens, out_att);
    k_ctx_part<<<dim3(4, 8, BB), 256>>>(value, out_att);
    k_ctx_final<<<BB * DD / 256, 256>>>(out);
}

// round 7
// speedup vs baseline: 1.1517x; 1.0126x over previous
#include <cuda_runtime.h>
#include <cuda_bf16.h>
#include <math.h>

#define BB 16
#define TT 4096
#define DD 512
#define CCH 10
#define FWD 100
#define KW 201          // 2*FW+1
#define NBLK 4          // N split: 4 tiles of 128 columns

// ---------------- device scratch (static, allowed) ----------------
__device__ __align__(16) __nv_bfloat16 g_Whi[DD * DD];
__device__ __align__(16) __nv_bfloat16 g_Wlo[DD * DD];
__device__ __align__(16) __nv_bfloat16 g_Vhi[(size_t)BB * TT * DD];
__device__ __align__(16) __nv_bfloat16 g_Vlo[(size_t)BB * TT * DD];
__device__ float g_dec[BB * DD];                 // dec projection + b_enc
__device__ float g_conv[BB * TT * CCH];          // conv features [b][t][c]
__device__ float g_epart[NBLK * BB * TT];        // partial logits per N-block
__device__ float g_ctxpart[8 * BB * DD];         // context partials per T-chunk

// ---------------- helpers ----------------
__device__ __forceinline__ unsigned pack_bf2(float x, float y) {
    __nv_bfloat162 h = __floats2bfloat162_rn(x, y);
    return *reinterpret_cast<unsigned*>(&h);
}
__device__ __forceinline__ float tanh_fast(float x) {
    float ax = fabsf(x);
    float z = __expf(-2.0f * ax);
    float t = __fdividef(1.0f - z, 1.0f + z);
    return copysignf(t, x);
}

// pure register op: NOT volatile, lets ptxas interleave freely
__device__ __forceinline__ void mma_bf16(float* d, const unsigned* a,
                                         unsigned b0, unsigned b1) {
    asm("mma.sync.aligned.m16n8k16.row.col.f32.bf16.bf16.f32 "
        "{%0,%1,%2,%3}, {%4,%5,%6,%7}, {%8,%9}, {%0,%1,%2,%3};\n"
        : "+f"(d[0]), "+f"(d[1]), "+f"(d[2]), "+f"(d[3])
        : "r"(a[0]), "r"(a[1]), "r"(a[2]), "r"(a[3]), "r"(b0), "r"(b1));
}

__device__ __forceinline__ void ldsm4(unsigned* r, unsigned addr) {
    asm volatile("ldmatrix.sync.aligned.m8n8.x4.shared.b16 {%0,%1,%2,%3}, [%4];\n"
                 : "=r"(r[0]), "=r"(r[1]), "=r"(r[2]), "=r"(r[3]) : "r"(addr));
}

#define CP_ASYNC16(sm, gm) \
    asm volatile("cp.async.cg.shared.global [%0], [%1], 16;\n" :: "r"(sm), "l"(gm))
#define CP_COMMIT() asm volatile("cp.async.commit_group;\n")
#define CP_WAIT(n)  asm volatile("cp.async.wait_group %0;\n" :: "n"(n))

// ---------------- kernel 1: split W_enc into bf16 hi/lo ----------------
__global__ void k_split(const float* __restrict__ W) {
    int i = blockIdx.x * blockDim.x + threadIdx.x;
    float w = W[i];
    __nv_bfloat16 hi = __float2bfloat16(w);
    g_Whi[i] = hi;
    g_Wlo[i] = __float2bfloat16(w - __bfloat162float(hi));
}

// ---------------- kernel 1b: split value into bf16 hi/lo ----------------
__global__ void __launch_bounds__(256) k_vsplit(const float* __restrict__ v) {
    size_t i = ((size_t)blockIdx.x * 256 + threadIdx.x) * 4;
    float4 x = *(const float4*)(v + i);
    __nv_bfloat16 h0 = __float2bfloat16(x.x);
    __nv_bfloat16 h1 = __float2bfloat16(x.y);
    __nv_bfloat16 h2 = __float2bfloat16(x.z);
    __nv_bfloat16 h3 = __float2bfloat16(x.w);
    __nv_bfloat162 ph0; ph0.x = h0; ph0.y = h1;
    __nv_bfloat162 ph1; ph1.x = h2; ph1.y = h3;
    uint2 hv = make_uint2(*(unsigned*)&ph0, *(unsigned*)&ph1);
    uint2 lv = make_uint2(pack_bf2(x.x - __bfloat162float(h0),
                                   x.y - __bfloat162float(h1)),
                          pack_bf2(x.z - __bfloat162float(h2),
                                   x.w - __bfloat162float(h3)));
    *reinterpret_cast<uint2*>(g_Vhi + i) = hv;
    *reinterpret_cast<uint2*>(g_Vlo + i) = lv;
}

// ---------------- kernel 2: dec projection + b_enc ----------------
__global__ void k_dec(const float* __restrict__ query,
                      const float* __restrict__ Wdec,
                      const float* __restrict__ b_enc) {
    __shared__ float q[DD];
    int b = blockIdx.x;
    int e = threadIdx.x;
    q[e] = query[b * DD + e];
    __syncthreads();
    float acc = b_enc[e];
    const float* wr = Wdec + e * DD;
#pragma unroll 8
    for (int d = 0; d < DD; ++d) acc += q[d] * wr[d];
    g_dec[b * DD + e] = acc;
}

// ---------------- kernel 3: location conv (att_prev -> [b][t][10]) ------
__global__ void k_conv(const float* __restrict__ att_prev,
                       const float* __restrict__ Wconv) {
    __shared__ float win[256 + 2 * FWD];
    __shared__ float wc[CCH * KW];
    int t0 = blockIdx.x * 256;
    int b = blockIdx.y;
    int tid = threadIdx.x;                 // 256
    for (int i = tid; i < 256 + 2 * FWD; i += 256) {
        int gidx = t0 - FWD + i;
        win[i] = (gidx >= 0 && gidx < TT) ? att_prev[b * TT + gidx] : 0.f;
    }
    for (int i = tid; i < CCH * KW; i += 256) wc[i] = Wconv[i];
    __syncthreads();
    float acc[CCH];
#pragma unroll
    for (int c = 0; c < CCH; ++c) acc[c] = 0.f;
    for (int h = 0; h < KW; ++h) {
        float x = win[tid + h];
#pragma unroll
        for (int c = 0; c < CCH; ++c) acc[c] += x * wc[c * KW + h];
    }
    float* o = &g_conv[(size_t)(b * TT + t0 + tid) * CCH];
#pragma unroll
    for (int c = 0; c < CCH; ++c) o[c] = acc[c];
}

// ---------------- kernel 4: fused split-bf16 GEMM + epilogue -> logits --
// 128(t) x 128(e) tile, KC=32, 4-stage cp.async pipeline, 1 barrier/iter,
// 256 threads (8 warps, 4m x 2n). Term-major MMA issue for independence.
// Grid: x = N-block (4 consecutive CTAs reuse the same A tile via L2).
#define KC 32
#define NCHUNK (DD / KC)       // 16
#define NSTAGE 4
#define ROWU 20                // padded row stride in uints (80 B)
#define ARR_BYTES (128u * ROWU * 4u)      // 10240 B per array
#define STAGE_BYTES (4u * ARR_BYTES)      // 40960 B: Ahi|Alo|Bhi|Blo
#define GEMM_SMEM (NSTAGE * STAGE_BYTES)  // 163840 B

__global__ void __launch_bounds__(256)
k_gemm(const float* __restrict__ Watt,
       const float* __restrict__ wg) {
    extern __shared__ __align__(16) char dsm[];
    int tid = threadIdx.x;
    int b = blockIdx.z;
    int e0 = blockIdx.x * 128;             // N-block fastest -> A L2 reuse
    int t0 = blockIdx.y * 128;
    int lane = tid & 31, warp = tid >> 5;
    int wm = warp & 3, wn = warp >> 2;     // 4m x 2n warps
    int g = lane >> 2, c = lane & 3;

    float acc[2][8][4];
#pragma unroll
    for (int mt = 0; mt < 2; ++mt)
#pragma unroll
        for (int nt = 0; nt < 8; ++nt)
#pragma unroll
            for (int q = 0; q < 4; ++q) acc[mt][nt][q] = 0.f;

    unsigned sbase = (unsigned)__cvta_generic_to_shared(dsm);

    int row0 = tid >> 2, seg = tid & 3;
    unsigned so0 = (unsigned)(row0 * ROWU * 4 + seg * 16);
    unsigned so1 = so0 + 64u * ROWU * 4u;
    const __nv_bfloat16* gA0hi =
        g_Vhi + ((size_t)(b * TT + t0 + row0)) * DD + seg * 8;
    const __nv_bfloat16* gA0lo =
        g_Vlo + ((size_t)(b * TT + t0 + row0)) * DD + seg * 8;
    const __nv_bfloat16* gB0hi = g_Whi + (size_t)(e0 + row0) * DD + seg * 8;
    const __nv_bfloat16* gB0lo = g_Wlo + (size_t)(e0 + row0) * DD + seg * 8;
    const size_t ro64 = (size_t)64 * DD;

#define ISSUE_STAGE(s, k0)                                                    \
    do {                                                                      \
        unsigned sb = sbase + (unsigned)(s) * STAGE_BYTES;                    \
        CP_ASYNC16(sb + so0, gA0hi + (k0));                                   \
        CP_ASYNC16(sb + so1, gA0hi + ro64 + (k0));                            \
        CP_ASYNC16(sb + ARR_BYTES + so0, gA0lo + (k0));                       \
        CP_ASYNC16(sb + ARR_BYTES + so1, gA0lo + ro64 + (k0));                \
        CP_ASYNC16(sb + 2 * ARR_BYTES + so0, gB0hi + (k0));                   \
        CP_ASYNC16(sb + 2 * ARR_BYTES + so1, gB0hi + ro64 + (k0));            \
        CP_ASYNC16(sb + 3 * ARR_BYTES + so0, gB0lo + (k0));                   \
        CP_ASYNC16(sb + 3 * ARR_BYTES + so1, gB0lo + ro64 + (k0));            \
    } while (0)

    int lr = ((lane >> 3) & 1) * 8 + (lane & 7);
    int lc = ((lane >> 4) & 1) * 4;

    ISSUE_STAGE(0, 0); CP_COMMIT();
    ISSUE_STAGE(1, KC); CP_COMMIT();
    ISSUE_STAGE(2, 2 * KC); CP_COMMIT();

    for (int it = 0; it < NCHUNK; ++it) {
        CP_WAIT(2);
        __syncthreads();
        unsigned stb = sbase + (unsigned)(it & 3) * STAGE_BYTES;

#pragma unroll
        for (int ks = 0; ks < 2; ++ks) {
            unsigned kso = (unsigned)(ks * 32);    // 8 uints = 32 bytes
            unsigned ahi[2][4], alo[2][4], bh[4][4], bl[4][4];
#pragma unroll
            for (int mt = 0; mt < 2; ++mt) {
                unsigned ao = stb +
                    (unsigned)((wm * 32 + mt * 16 + lr) * ROWU * 4 + lc * 4) + kso;
                ldsm4(ahi[mt], ao);
                ldsm4(alo[mt], ao + ARR_BYTES);
            }
#pragma unroll
            for (int ntp = 0; ntp < 4; ++ntp) {
                unsigned bo = stb + 2 * ARR_BYTES +
                    (unsigned)((wn * 64 + ntp * 16 + lr) * ROWU * 4 + lc * 4) + kso;
                ldsm4(bh[ntp], bo);
                ldsm4(bl[ntp], bo + ARR_BYTES);
            }
            // term-major issue: consecutive MMAs hit different accumulators
#pragma unroll
            for (int ntp = 0; ntp < 4; ++ntp)
#pragma unroll
                for (int sub = 0; sub < 2; ++sub)
#pragma unroll
                    for (int mt = 0; mt < 2; ++mt)
                        mma_bf16(acc[mt][ntp * 2 + sub], ahi[mt],
                                 bh[ntp][sub], bh[ntp][2 + sub]);
#pragma unroll
            for (int ntp = 0; ntp < 4; ++ntp)
#pragma unroll
                for (int sub = 0; sub < 2; ++sub)
#pragma unroll
                    for (int mt = 0; mt < 2; ++mt)
                        mma_bf16(acc[mt][ntp * 2 + sub], ahi[mt],
                                 bl[ntp][sub], bl[ntp][2 + sub]);
#pragma unroll
            for (int ntp = 0; ntp < 4; ++ntp)
#pragma unroll
                for (int sub = 0; sub < 2; ++sub)
#pragma unroll
                    for (int mt = 0; mt < 2; ++mt)
                        mma_bf16(acc[mt][ntp * 2 + sub], alo[mt],
                                 bh[ntp][sub], bh[ntp][2 + sub]);
        }
        if (it + 3 < NCHUNK) ISSUE_STAGE((it + 3) & 3, (it + 3) * KC);
        CP_COMMIT();
    }
    __syncthreads();   // all stages consumed; safe to overlay epilogue

    // ---- epilogue smem overlay on dynamic smem ----
    float* econv = (float*)dsm;              // [128][10]
    float* ewatt = econv + 1280;             // [128][10]
    float* edec  = ewatt + 1280;             // [128]
    float* ewg   = edec + 128;               // [128]
    float* ered  = ewg + 128;                // [128][2]

    for (int i = tid; i < 1280; i += 256) {
        int row = i / 10, cc = i - row * 10;
        econv[i] = g_conv[(size_t)(b * TT + t0 + row) * CCH + cc];
        ewatt[i] = Watt[(e0 + row) * CCH + cc];
    }
    if (tid < 128) {
        edec[tid] = g_dec[b * DD + e0 + tid];
        ewg[tid] = wg[e0 + tid];
    }
    __syncthreads();

    float rowsum[2][2];
#pragma unroll
    for (int mt = 0; mt < 2; ++mt)
#pragma unroll
        for (int rr = 0; rr < 2; ++rr) {
            int rowl = wm * 32 + mt * 16 + rr * 8 + g;
            float sacc = 0.f;
#pragma unroll
            for (int nt = 0; nt < 8; ++nt)
#pragma unroll
                for (int q = 0; q < 2; ++q) {
                    int el = wn * 64 + nt * 8 + 2 * c + q;
                    float v = acc[mt][nt][rr * 2 + q] + edec[el];
#pragma unroll
                    for (int cc = 0; cc < CCH; ++cc)
                        v += econv[rowl * 10 + cc] * ewatt[el * 10 + cc];
                    sacc += ewg[el] * tanh_fast(v);
                }
            rowsum[mt][rr] = sacc;
        }
#pragma unroll
    for (int mt = 0; mt < 2; ++mt)
#pragma unroll
        for (int rr = 0; rr < 2; ++rr) {
            float v = rowsum[mt][rr];
            v += __shfl_xor_sync(0xffffffffu, v, 1);
            v += __shfl_xor_sync(0xffffffffu, v, 2);
            rowsum[mt][rr] = v;
        }
    if (c == 0) {
#pragma unroll
        for (int mt = 0; mt < 2; ++mt)
#pragma unroll
            for (int rr = 0; rr < 2; ++rr)
                ered[(wm * 32 + mt * 16 + rr * 8 + g) * 2 + wn] = rowsum[mt][rr];
    }
    __syncthreads();
    if (tid < 128) {
        float val = ered[tid * 2] + ered[tid * 2 + 1];
        g_epart[((size_t)blockIdx.x * BB + b) * TT + t0 + tid] = val;
    }
}

// ---------------- kernel 5: masked sharpened softmax ----------------
__global__ void k_softmax(const int* __restrict__ lens,
                          float* __restrict__ out_att) {
    int b = blockIdx.x;
    int tid = threadIdx.x;            // 256
    int len = lens[b];
    __shared__ float sred[256];
    float ev[16];
    float lmax = -INFINITY;
#pragma unroll
    for (int i = 0; i < 16; ++i) {
        int t = tid + i * 256;
        float e = g_epart[(0 * BB + b) * TT + t] +
                  g_epart[(1 * BB + b) * TT + t] +
                  g_epart[(2 * BB + b) * TT + t] +
                  g_epart[(3 * BB + b) * TT + t];
        e *= 2.0f;                    // sharpening
        ev[i] = (t < len) ? e : -INFINITY;
        lmax = fmaxf(lmax, ev[i]);
    }
    sred[tid] = lmax;
    __syncthreads();
    for (int s = 128; s > 0; s >>= 1) {
        if (tid < s) sred[tid] = fmaxf(sred[tid], sred[tid + s]);
        __syncthreads();
    }
    float m = sred[0];
    __syncthreads();
    float lsum = 0.f;
#pragma unroll
    for (int i = 0; i < 16; ++i) {
        float p = expf(ev[i] - m);
        ev[i] = p;
        lsum += p;
    }
    sred[tid] = lsum;
    __syncthreads();
    for (int s = 128; s > 0; s >>= 1) {
        if (tid < s) sred[tid] += sred[tid + s];
        __syncthreads();
    }
    float inv = 1.f / sred[0];
#pragma unroll
    for (int i = 0; i < 16; ++i)
        out_att[b * TT + tid + i * 256] = ev[i] * inv;
}

// ---------------- kernel 6/7: context = value^T @ weights ----------------
__global__ void k_ctx_part(const float* __restrict__ value,
                           const float* __restrict__ att) {
    int dch = blockIdx.x, tch = blockIdx.y, b = blockIdx.z;
    int dl = threadIdx.x & 127;
    int tl = threadIdx.x >> 7;
    int d = dch * 128 + dl;
    const float* vb = value + (size_t)b * TT * DD;
    const float* ab = att + b * TT;
    float acc = 0.f;
    int tbase = tch * 512;
    for (int t = tbase + tl; t < tbase + 512; t += 2)
        acc += vb[(size_t)t * DD + d] * ab[t];
    __shared__ float s[256];
    s[threadIdx.x] = acc;
    __syncthreads();
    if (tl == 0)
        g_ctxpart[((size_t)tch * BB + b) * DD + d] = s[dl] + s[dl + 128];
}

__global__ void k_ctx_final(float* __restrict__ out) {
    int idx = blockIdx.x * 256 + threadIdx.x;
    float v = 0.f;
#pragma unroll
    for (int p = 0; p < 8; ++p) v += g_ctxpart[p * BB * DD + idx];
    out[idx] = v;
}

// ---------------- launch ----------------
extern "C" void kernel_launch(void* const* d_in, const int* in_sizes, int n_in,
                              void* d_out, int out_size) {
    const float* value    = (const float*)d_in[0];
    const float* query    = (const float*)d_in[1];
    const int*   lens     = (const int*)d_in[2];
    const float* att_prev = (const float*)d_in[3];
    const float* W_enc    = (const float*)d_in[4];
    const float* b_enc    = (const float*)d_in[5];
    const float* W_dec    = (const float*)d_in[6];
    const float* W_att    = (const float*)d_in[7];
    const float* W_conv   = (const float*)d_in[8];
    const float* w_g      = (const float*)d_in[9];
    // d_in[10] = b_g: uniform logit shift, cancels in softmax.

    float* out = (float*)d_out;
    float* out_att = out + BB * DD;

    cudaFuncSetAttribute(k_gemm, cudaFuncAttributeMaxDynamicSharedMemorySize,
                         GEMM_SMEM);

    k_split<<<512, 512>>>(W_enc);
    k_vsplit<<<(BB * TT * DD) / (4 * 256), 256>>>(value);
    k_dec<<<BB, DD>>>(query, W_dec, b_enc);
    k_conv<<<dim3(TT / 256, BB), 256>>>(att_prev, W_conv);
    k_gemm<<<dim3(NBLK, TT / 128, BB), 256, GEMM_SMEM>>>(W_att, w_g);
    k_softmax<<<BB, 256>>>(lens, out_att);
    k_ctx_part<<<dim3(4, 8, BB), 256>>>(value, out_att);
    k_ctx_final<<<BB * DD / 256, 256>>>(out);
}